// round 9
// baseline (speedup 1.0000x reference)
#include <cuda_runtime.h>

// TemporalScaledDotProductforCrossAttention — GB300 fused kernel, v4.
// TWO sites per CTA; warps 0,1 -> site A, warps 2,3 -> site B.
// Each warp packs 2 variants in half-warps; each lane owns TWO q-rows (g=2).
// v4: smem cut to 44.5KB (V tiles stride-16) + regs capped 102 -> 5 CTAs/SM
//     (20 warps, +25% issue capacity vs R8's 16). Output phase i-outer/k-inner
//     to shrink accumulator live set. Packed fma.rn.f32x2 throughout.

static constexpr int SITE_F4 = 1406;   // float4 per site (see base table)
// tile bases (f4), strides: A-capable tiles stride 17, V-only tiles stride 16.
// bases mod 8 chosen so each warp's two B tiles hit disjoint bank quadrants:
//   t0 Qf  @0    (c=0, s17)   t1 Kf @204  (c=4, s17)   t2 Vf @408  (c=0, s16)
//   t3 Qs  @600  (c=0, s17)   t4 Ks @806  (c=6, s17)   t5 Vs @1010 (c=2, s16)
//   t6 Qfs @1202 (c=2, s17)
static constexpr int B0 = 0, B1 = 204, B2t = 408, B3 = 600, B4 = 806, B5 = 1010, B6 = 1202;

__device__ __forceinline__ unsigned long long fma2(unsigned long long a,
                                                   unsigned long long b,
                                                   unsigned long long c) {
    unsigned long long d;
    asm("fma.rn.f32x2 %0, %1, %2, %3;" : "=l"(d) : "l"(a), "l"(b), "l"(c));
    return d;
}
__device__ __forceinline__ unsigned long long pack2(float x, float y) {
    unsigned long long r;
    asm("mov.b64 %0, {%1, %2};" : "=l"(r) : "f"(x), "f"(y));
    return r;
}
__device__ __forceinline__ float2 unpack2(unsigned long long v) {
    float2 r;
    asm("mov.b64 {%0, %1}, %2;" : "=f"(r.x), "=f"(r.y) : "l"(v));
    return r;
}

__global__ __launch_bounds__(128, 5)
void tsdp_kernel(const float* __restrict__ Qf, const float* __restrict__ Kf,
                 const float* __restrict__ Vf, const float* __restrict__ Qs,
                 const float* __restrict__ Ks, const float* __restrict__ Vs,
                 const float* __restrict__ Kj, const float* __restrict__ Vfp,
                 const int* __restrict__ mask, float* __restrict__ out,
                 int nsite)
{
    __shared__ float4 T[2 * SITE_F4];
    __shared__ int smask[144];

    const int site0 = blockIdx.x * 2;
    const int tid   = threadIdx.x;

    // ---- Stage BOTH sites: gmem -> smem (coalesced float4) ----
    #pragma unroll
    for (int rep = 0; rep < 3; rep++) {
        int f  = tid + rep * 128;              // [0, 384)
        int sl = (f >= 192) ? 1 : 0;
        int fl = f - 192 * sl;
        int r  = fl >> 4, cc = fl & 15;
        int i17 = sl * SITE_F4 + r * 17 + cc;
        int i16 = sl * SITE_F4 + r * 16 + cc;
        long long g = (long long)(site0 + sl) * 192 + fl;

        T[B0  + i17] = ((const float4*)Qf)[g];
        T[B1  + i17] = ((const float4*)Kf)[g];
        T[B2t + i16] = ((const float4*)Vf)[g];
        float4 v = ((const float4*)Qs)[g];
        T[B3  + i17] = v;
        T[B4  + i17] = ((const float4*)Ks)[g];
        T[B5  + i16] = ((const float4*)Vs)[g];
        // Qfs[k][d] = Kj[k] * (x - x*x / (Vfp[k] + 1e-5))
        float kj    = __ldg(Kj + r);
        float denom = __ldg(Vfp + r) + 1e-5f;
        float4 w;
        w.x = kj * (v.x - (v.x * v.x) / denom);
        w.y = kj * (v.y - (v.y * v.y) / denom);
        w.z = kj * (v.z - (v.z * v.z) / denom);
        w.w = kj * (v.w - (v.w * v.w) / denom);
        T[B6 + i17] = w;
    }
    for (int i = tid; i < 144; i += 128) smask[i] = mask[i];
    __syncthreads();

    const int warp = tid >> 5;
    const int lane = tid & 31;
    if (lane >= 24) return;                  // no further block syncs

    const int siteLoc = warp >> 1;           // 0 or 1
    const int pairId  = warp & 1;            // 0: ff+fs, 1: sf+ss
    const int site    = site0 + siteLoc;

    const int sub = (lane >= 12) ? 1 : 0;    // variant within the pair
    const int l   = lane - 12 * sub;
    const int qp  = l >> 1;                  // q-pair 0..5
    const int h   = l & 1;                   // D-half
    const int q0  = 2 * qp, q1 = q0 + 1;
    const int rot = 4 * h;

    // operand tile bases + output quarter per (pairId, sub)
    int aB, bB, vB, outq;
    if (pairId == 0) {
        if (!sub) { aB = B0; bB = B1; vB = B2t; outq = 0; }  // ff: Qf·Kf^T  -> Vf
        else      { aB = B1; bB = B6; vB = B2t; outq = 1; }  // fs: Kf·Qfs^T -> Vf
    } else {
        if (!sub) { aB = B4; bB = B0; vB = B5;  outq = 2; }  // sf: Ks·Qf^T  -> Vs
        else      { aB = B3; bB = B4; vB = B5;  outq = 3; }  // ss: Qs·Ks^T  -> Vs
    }
    const float4* Ts = T + siteLoc * SITE_F4;
    const ulonglong2* A2 = (const ulonglong2*)(Ts + aB);
    const ulonglong2* Bv = (const ulonglong2*)(Ts + bB);
    const ulonglong2* V2 = (const ulonglong2*)(Ts + vB);

    // ---- Scores: chunked A hoist; each B chunk feeds both q-rows ----
    float s0[12], s1[12];
    #pragma unroll
    for (int k = 0; k < 12; k++) { s0[k] = 0.0f; s1[k] = 0.0f; }

    #pragma unroll
    for (int ch = 0; ch < 2; ch++) {
        ulonglong2 a0[4], a1[4];
        int jj[4];
        #pragma unroll
        for (int i = 0; i < 4; i++) {
            jj[i] = (ch * 4 + i + rot) & 7;
            a0[i] = A2[q0 * 17 + h * 8 + jj[i]];
            a1[i] = A2[q1 * 17 + h * 8 + jj[i]];
        }
        #pragma unroll
        for (int k = 0; k < 12; k++) {
            unsigned long long acc0 = 0ULL, acc1 = 0ULL;
            #pragma unroll
            for (int i = 0; i < 4; i++) {
                ulonglong2 b = Bv[k * 17 + h * 8 + jj[i]];   // broadcast pairs
                acc0 = fma2(a0[i].x, b.x, acc0);
                acc0 = fma2(a0[i].y, b.y, acc0);
                acc1 = fma2(a1[i].x, b.x, acc1);
                acc1 = fma2(a1[i].y, b.y, acc1);
            }
            float2 p0 = unpack2(acc0), p1 = unpack2(acc1);
            s0[k] += p0.x + p0.y;
            s1[k] += p1.x + p1.y;
        }
    }

    // cross-half reduce + scale + exact mask select
    #pragma unroll
    for (int k = 0; k < 12; k++) {
        float v0 = s0[k] + __shfl_xor_sync(0x00ffffffu, s0[k], 1);
        float v1 = s1[k] + __shfl_xor_sync(0x00ffffffu, s1[k], 1);
        s0[k] = (smask[q0 * 12 + k] == 1) ? -1e9f : v0 * 0.125f;
        s1[k] = (smask[q1 * 12 + k] == 1) ? -1e9f : v1 * 0.125f;
    }

    // ---- Softmax per row; pre-scale weights by 1/sum ----
    float mx0 = s0[0], mx1 = s1[0];
    #pragma unroll
    for (int k = 1; k < 12; k++) { mx0 = fmaxf(mx0, s0[k]); mx1 = fmaxf(mx1, s1[k]); }
    float sum0 = 0.f, sum1 = 0.f;
    #pragma unroll
    for (int k = 0; k < 12; k++) {
        s0[k] = __expf(s0[k] - mx0); sum0 += s0[k];
        s1[k] = __expf(s1[k] - mx1); sum1 += s1[k];
    }
    const float rs0 = 1.0f / sum0, rs1 = 1.0f / sum1;
    #pragma unroll
    for (int k = 0; k < 12; k++) { s0[k] *= rs0; s1[k] *= rs1; }

    // ---- Output: i-outer (chunks of 2), k-inner; small accumulator live set ----
    float4* ob = (float4*)out + ((long long)outq * nsite + site) * 192 + h * 8;
    float4* o0 = ob + q0 * 16;
    float4* o1 = ob + q1 * 16;

    #pragma unroll
    for (int ib = 0; ib < 4; ib++) {
        const int jA = (2 * ib + rot) & 7;
        const int jBk = (2 * ib + 1 + rot) & 7;
        unsigned long long cA0x = 0ULL, cA0y = 0ULL, cA1x = 0ULL, cA1y = 0ULL;
        unsigned long long cB0x = 0ULL, cB0y = 0ULL, cB1x = 0ULL, cB1y = 0ULL;
        #pragma unroll
        for (int k = 0; k < 12; k++) {
            unsigned long long z0p = pack2(s0[k], s0[k]);
            unsigned long long z1p = pack2(s1[k], s1[k]);
            ulonglong2 vA = V2[k * 16 + h * 8 + jA];     // broadcast pairs
            ulonglong2 vB = V2[k * 16 + h * 8 + jBk];
            cA0x = fma2(z0p, vA.x, cA0x);  cA0y = fma2(z0p, vA.y, cA0y);
            cA1x = fma2(z1p, vA.x, cA1x);  cA1y = fma2(z1p, vA.y, cA1y);
            cB0x = fma2(z0p, vB.x, cB0x);  cB0y = fma2(z0p, vB.y, cB0y);
            cB1x = fma2(z1p, vB.x, cB1x);  cB1y = fma2(z1p, vB.y, cB1y);
        }
        float2 a, b;
        a = unpack2(cA0x); b = unpack2(cA0y); o0[jA]  = make_float4(a.x, a.y, b.x, b.y);
        a = unpack2(cA1x); b = unpack2(cA1y); o1[jA]  = make_float4(a.x, a.y, b.x, b.y);
        a = unpack2(cB0x); b = unpack2(cB0y); o0[jBk] = make_float4(a.x, a.y, b.x, b.y);
        a = unpack2(cB1x); b = unpack2(cB1y); o1[jBk] = make_float4(a.x, a.y, b.x, b.y);
    }
}

extern "C" void kernel_launch(void* const* d_in, const int* in_sizes, int n_in,
                              void* d_out, int out_size) {
    const int nsite = in_sizes[0] / 768;   // B*H*L1 = 39296 (even)
    tsdp_kernel<<<nsite / 2, 128>>>(
        (const float*)d_in[0], (const float*)d_in[1], (const float*)d_in[2],
        (const float*)d_in[3], (const float*)d_in[4], (const float*)d_in[5],
        (const float*)d_in[6], (const float*)d_in[7],
        (const int*)d_in[8],
        (float*)d_out, nsite);
}

// round 10
// speedup vs baseline: 1.2313x; 1.2313x over previous
#include <cuda_runtime.h>
#include <cstdint>

// TemporalScaledDotProductforCrossAttention — GB300 fused kernel, v5.
// = R8 (best, 312us) compute structure + cp.async staging (kills the
//   serialized LDG->STS latency chain that capped issue at 38%).
// TWO sites per CTA; warps 0,1 -> site A, warps 2,3 -> site B.
// Each warp packs 2 variants in half-warps; each lane owns TWO q-rows (g=2).
// Packed fma.rn.f32x2; k-outer output phase (R9's i-outer variant regressed).

static constexpr int STR4 = 17;    // padded float4 stride per 12-row tile
__device__ __forceinline__ constexpr int TB(int t) { return t * 204 + (t >= 4 ? 2 : 0); }
static constexpr int SITE_F4 = 6 * 204 + 2 + 204;   // 1430 float4 per site

__device__ __forceinline__ unsigned long long fma2(unsigned long long a,
                                                   unsigned long long b,
                                                   unsigned long long c) {
    unsigned long long d;
    asm("fma.rn.f32x2 %0, %1, %2, %3;" : "=l"(d) : "l"(a), "l"(b), "l"(c));
    return d;
}
__device__ __forceinline__ unsigned long long pack2(float x, float y) {
    unsigned long long r;
    asm("mov.b64 %0, {%1, %2};" : "=l"(r) : "f"(x), "f"(y));
    return r;
}
__device__ __forceinline__ float2 unpack2(unsigned long long v) {
    float2 r;
    asm("mov.b64 {%0, %1}, %2;" : "=f"(r.x), "=f"(r.y) : "l"(v));
    return r;
}
__device__ __forceinline__ void cp16(uint32_t smem_addr, const void* gptr) {
    asm volatile("cp.async.cg.shared.global [%0], [%1], 16;"
                 :: "r"(smem_addr), "l"(gptr));
}

__global__ __launch_bounds__(128, 4)
void tsdp_kernel(const float* __restrict__ Qf, const float* __restrict__ Kf,
                 const float* __restrict__ Vf, const float* __restrict__ Qs,
                 const float* __restrict__ Ks, const float* __restrict__ Vs,
                 const float* __restrict__ Kj, const float* __restrict__ Vfp,
                 const int* __restrict__ mask, float* __restrict__ out,
                 int nsite)
{
    // tiles per site: 0=Qf 1=Kf 2=Vf 3=Qs 4=Ks 5=Vs 6=Qfs(flow-speed)
    __shared__ float4 T[2 * SITE_F4];
    __shared__ int smask[144];

    const int site0 = blockIdx.x * 2;
    const int tid   = threadIdx.x;

    // ---- Stage BOTH sites via cp.async (no LDG->STS register chain) ----
    {
        const uint32_t sb = (uint32_t)__cvta_generic_to_shared(T);
        #pragma unroll
        for (int rep = 0; rep < 3; rep++) {
            int f  = tid + rep * 128;              // [0, 384)
            int sl = (f >= 192) ? 1 : 0;
            int fl = f - 192 * sl;
            int r  = fl >> 4, cc = fl & 15;
            int i17 = sl * SITE_F4 + r * STR4 + cc;
            long long g = (long long)(site0 + sl) * 192 + fl;
            uint32_t sa = sb + (uint32_t)i17 * 16u;
            cp16(sa + TB(0) * 16u, (const float4*)Qf + g);
            cp16(sa + TB(1) * 16u, (const float4*)Kf + g);
            cp16(sa + TB(2) * 16u, (const float4*)Vf + g);
            cp16(sa + TB(3) * 16u, (const float4*)Qs + g);
            cp16(sa + TB(4) * 16u, (const float4*)Ks + g);
            cp16(sa + TB(5) * 16u, (const float4*)Vs + g);
        }
        asm volatile("cp.async.commit_group;" ::: "memory");
    }
    // mask (tiny) via normal LDG/STS — overlaps with the async copies
    for (int i = tid; i < 144; i += 128) smask[i] = mask[i];
    asm volatile("cp.async.wait_group 0;" ::: "memory");
    __syncthreads();

    // ---- Build flow-speed tile 6 from resident Qs tile ----
    #pragma unroll
    for (int rep = 0; rep < 3; rep++) {
        int f  = tid + rep * 128;
        int sl = (f >= 192) ? 1 : 0;
        int fl = f - 192 * sl;
        int r  = fl >> 4, cc = fl & 15;
        int i17 = sl * SITE_F4 + r * STR4 + cc;
        float4 v = T[TB(3) + i17];
        float kj    = __ldg(Kj + r);
        float denom = __ldg(Vfp + r) + 1e-5f;
        float4 w;
        w.x = kj * (v.x - (v.x * v.x) / denom);
        w.y = kj * (v.y - (v.y * v.y) / denom);
        w.z = kj * (v.z - (v.z * v.z) / denom);
        w.w = kj * (v.w - (v.w * v.w) / denom);
        T[TB(6) + i17] = w;
    }
    __syncthreads();

    const int warp = tid >> 5;
    const int lane = tid & 31;
    if (lane >= 24) return;                  // no further block syncs

    const int siteLoc = warp >> 1;           // 0 or 1
    const int pairId  = warp & 1;            // 0: ff+fs, 1: sf+ss
    const int site    = site0 + siteLoc;

    const int sub = (lane >= 12) ? 1 : 0;    // variant within the pair
    const int l   = lane - 12 * sub;
    const int qp  = l >> 1;                  // q-pair 0..5
    const int h   = l & 1;                   // D-half
    const int q0  = 2 * qp, q1 = q0 + 1;
    const int rot = 4 * h;

    // operand tiles + output quarter per (pairId, sub)
    int aT, bT, vT, outq;
    if (pairId == 0) {
        if (!sub) { aT = 0; bT = 1; vT = 2; outq = 0; }   // ff: Qf·Kf^T  -> Vf
        else      { aT = 1; bT = 6; vT = 2; outq = 1; }   // fs: Kf·Qfs^T -> Vf
    } else {
        if (!sub) { aT = 4; bT = 0; vT = 5; outq = 2; }   // sf: Ks·Qf^T  -> Vs
        else      { aT = 3; bT = 4; vT = 5; outq = 3; }   // ss: Qs·Ks^T  -> Vs
    }
    const float4* Ts = T + siteLoc * SITE_F4;
    const ulonglong2* A2 = (const ulonglong2*)(Ts + TB(aT));
    const ulonglong2* B2 = (const ulonglong2*)(Ts + TB(bT));
    const ulonglong2* V2 = (const ulonglong2*)(Ts + TB(vT));

    // ---- Scores: chunked A hoist; each B chunk feeds both q-rows ----
    float s0[12], s1[12];
    #pragma unroll
    for (int k = 0; k < 12; k++) { s0[k] = 0.0f; s1[k] = 0.0f; }

    #pragma unroll
    for (int ch = 0; ch < 2; ch++) {
        ulonglong2 a0[4], a1[4];
        int jj[4];
        #pragma unroll
        for (int i = 0; i < 4; i++) {
            jj[i] = (ch * 4 + i + rot) & 7;
            a0[i] = A2[q0 * STR4 + h * 8 + jj[i]];
            a1[i] = A2[q1 * STR4 + h * 8 + jj[i]];
        }
        #pragma unroll
        for (int k = 0; k < 12; k++) {
            unsigned long long acc0 = 0ULL, acc1 = 0ULL;
            #pragma unroll
            for (int i = 0; i < 4; i++) {
                ulonglong2 b = B2[k * STR4 + h * 8 + jj[i]];
                acc0 = fma2(a0[i].x, b.x, acc0);
                acc0 = fma2(a0[i].y, b.y, acc0);
                acc1 = fma2(a1[i].x, b.x, acc1);
                acc1 = fma2(a1[i].y, b.y, acc1);
            }
            float2 p0 = unpack2(acc0), p1 = unpack2(acc1);
            s0[k] += p0.x + p0.y;
            s1[k] += p1.x + p1.y;
        }
    }

    // cross-half reduce + scale + exact mask select
    #pragma unroll
    for (int k = 0; k < 12; k++) {
        float v0 = s0[k] + __shfl_xor_sync(0x00ffffffu, s0[k], 1);
        float v1 = s1[k] + __shfl_xor_sync(0x00ffffffu, s1[k], 1);
        s0[k] = (smask[q0 * 12 + k] == 1) ? -1e9f : v0 * 0.125f;
        s1[k] = (smask[q1 * 12 + k] == 1) ? -1e9f : v1 * 0.125f;
    }

    // ---- Softmax per row (both h-lanes redundantly); pre-scale by 1/sum ----
    float mx0 = s0[0], mx1 = s1[0];
    #pragma unroll
    for (int k = 1; k < 12; k++) { mx0 = fmaxf(mx0, s0[k]); mx1 = fmaxf(mx1, s1[k]); }
    float sum0 = 0.f, sum1 = 0.f;
    #pragma unroll
    for (int k = 0; k < 12; k++) {
        s0[k] = __expf(s0[k] - mx0); sum0 += s0[k];
        s1[k] = __expf(s1[k] - mx1); sum1 += s1[k];
    }
    const float rs0 = 1.0f / sum0, rs1 = 1.0f / sum1;
    #pragma unroll
    for (int k = 0; k < 12; k++) { s0[k] *= rs0; s1[k] *= rs1; }

    // ---- Output (k-outer): each V chunk feeds both q-rows ----
    ulonglong2 c0[8], c1[8];
    #pragma unroll
    for (int i = 0; i < 8; i++) { c0[i].x = c0[i].y = 0ULL; c1[i].x = c1[i].y = 0ULL; }

    #pragma unroll
    for (int k = 0; k < 12; k++) {
        unsigned long long z0p = pack2(s0[k], s0[k]);
        unsigned long long z1p = pack2(s1[k], s1[k]);
        #pragma unroll
        for (int i = 0; i < 8; i++) {
            ulonglong2 v = V2[k * STR4 + h * 8 + ((i + rot) & 7)];
            c0[i].x = fma2(z0p, v.x, c0[i].x);
            c0[i].y = fma2(z0p, v.y, c0[i].y);
            c1[i].x = fma2(z1p, v.x, c1[i].x);
            c1[i].y = fma2(z1p, v.y, c1[i].y);
        }
    }

    // ---- Store both rows (un-rotate); quarters ordered (ff, fs, sf, ss) ----
    float4* ob = (float4*)out + ((long long)outq * nsite + site) * 192 + h * 8;
    float4* o0 = ob + q0 * 16;
    float4* o1 = ob + q1 * 16;
    #pragma unroll
    for (int i = 0; i < 8; i++) {
        int j = (i + rot) & 7;
        float2 lo0 = unpack2(c0[i].x), hi0 = unpack2(c0[i].y);
        float2 lo1 = unpack2(c1[i].x), hi1 = unpack2(c1[i].y);
        o0[j] = make_float4(lo0.x, lo0.y, hi0.x, hi0.y);
        o1[j] = make_float4(lo1.x, lo1.y, hi1.x, hi1.y);
    }
}

extern "C" void kernel_launch(void* const* d_in, const int* in_sizes, int n_in,
                              void* d_out, int out_size) {
    const int nsite = in_sizes[0] / 768;   // B*H*L1 = 39296 (even)
    tsdp_kernel<<<nsite / 2, 128>>>(
        (const float*)d_in[0], (const float*)d_in[1], (const float*)d_in[2],
        (const float*)d_in[3], (const float*)d_in[4], (const float*)d_in[5],
        (const float*)d_in[6], (const float*)d_in[7],
        (const int*)d_in[8],
        (float*)d_out, nsite);
}

// round 14
// speedup vs baseline: 1.3196x; 1.0717x over previous
#include <cuda_runtime.h>
#include <cstdint>

// TemporalScaledDotProductforCrossAttention — GB300 fused kernel, v6.
// = R10 compute (best, 279us) + warp-pair decoupled staging:
//   warps {0,1} own site A, warps {2,3} own site B — each pair cp.asyncs its
//   own tiles, waits only its own group, syncs via 64-thread named barrier.
//   No block-wide __syncthreads; pairs free-run so one pair's stage latency
//   hides under the other pair's compute. Kj / 1/(Vfp+eps) prefetched to smem.
// Each warp packs 2 variants in half-warps; each lane owns TWO q-rows (g=2).
// Packed fma.rn.f32x2 throughout; k-outer output phase.

static constexpr int STR4 = 17;    // padded float4 stride per 12-row tile
__device__ __forceinline__ constexpr int TB(int t) { return t * 204 + (t >= 4 ? 2 : 0); }
static constexpr int SITE_F4 = 6 * 204 + 2 + 204;   // 1430 float4 per site

__device__ __forceinline__ unsigned long long fma2(unsigned long long a,
                                                   unsigned long long b,
                                                   unsigned long long c) {
    unsigned long long d;
    asm("fma.rn.f32x2 %0, %1, %2, %3;" : "=l"(d) : "l"(a), "l"(b), "l"(c));
    return d;
}
__device__ __forceinline__ unsigned long long pack2(float x, float y) {
    unsigned long long r;
    asm("mov.b64 %0, {%1, %2};" : "=l"(r) : "f"(x), "f"(y));
    return r;
}
__device__ __forceinline__ float2 unpack2(unsigned long long v) {
    float2 r;
    asm("mov.b64 {%0, %1}, %2;" : "=f"(r.x), "=f"(r.y) : "l"(v));
    return r;
}
__device__ __forceinline__ void cp16(uint32_t smem_addr, const void* gptr) {
    asm volatile("cp.async.cg.shared.global [%0], [%1], 16;"
                 :: "r"(smem_addr), "l"(gptr));
}

__global__ __launch_bounds__(128, 4)
void tsdp_kernel(const float* __restrict__ Qf, const float* __restrict__ Kf,
                 const float* __restrict__ Vf, const float* __restrict__ Qs,
                 const float* __restrict__ Ks, const float* __restrict__ Vs,
                 const float* __restrict__ Kj, const float* __restrict__ Vfp,
                 const int* __restrict__ mask, float* __restrict__ out,
                 int nsite)
{
    // tiles per site: 0=Qf 1=Kf 2=Vf 3=Qs 4=Ks 5=Vs 6=Qfs(flow-speed)
    __shared__ float4 T[2 * SITE_F4];
    __shared__ int   smaskP[2][144];    // per-pair copy (pairs stay independent)
    __shared__ float sKj[2][12], sInv[2][12];

    const int site0 = blockIdx.x * 2;
    const int tid   = threadIdx.x;
    const int warp  = tid >> 5;
    const int lane  = tid & 31;
    const int pair  = warp >> 1;        // 0: site A (warps 0,1), 1: site B (warps 2,3)
    const int wl    = tid & 63;         // thread index within the pair
    const int site  = site0 + pair;

    // ---- Stage THIS pair's site via cp.async ----
    {
        const uint32_t sb = (uint32_t)__cvta_generic_to_shared(T)
                          + (uint32_t)(pair * SITE_F4) * 16u;
        #pragma unroll
        for (int rep = 0; rep < 3; rep++) {
            int f  = wl + rep * 64;                // [0, 192)
            int r  = f >> 4, cc = f & 15;
            uint32_t sa = sb + (uint32_t)(r * STR4 + cc) * 16u;
            long long g = (long long)site * 192 + f;
            cp16(sa + TB(0) * 16u, (const float4*)Qf + g);
            cp16(sa + TB(1) * 16u, (const float4*)Kf + g);
            cp16(sa + TB(2) * 16u, (const float4*)Vf + g);
            cp16(sa + TB(3) * 16u, (const float4*)Qs + g);
            cp16(sa + TB(4) * 16u, (const float4*)Ks + g);
            cp16(sa + TB(5) * 16u, (const float4*)Vs + g);
        }
        asm volatile("cp.async.commit_group;" ::: "memory");
    }
    // overlap with copy latency: mask + flow-speed params (L2-hot LDGs)
    for (int i = wl; i < 144; i += 64) smaskP[pair][i] = mask[i];
    if (wl < 12) {
        sKj[pair][wl]  = __ldg(Kj + wl);
        sInv[pair][wl] = 1.0f / (__ldg(Vfp + wl) + 1e-5f);
    }
    asm volatile("cp.async.wait_group 0;" ::: "memory");
    asm volatile("bar.sync %0, 64;" :: "r"(1 + pair) : "memory");

    // ---- Build flow-speed tile 6 from resident Qs tile (pair-local) ----
    #pragma unroll
    for (int rep = 0; rep < 3; rep++) {
        int f  = wl + rep * 64;
        int r  = f >> 4, cc = f & 15;
        int i17 = pair * SITE_F4 + r * STR4 + cc;
        float4 v = T[TB(3) + i17];
        float kj  = sKj[pair][r];
        float inv = sInv[pair][r];
        float4 w;
        w.x = kj * (v.x - (v.x * v.x) * inv);
        w.y = kj * (v.y - (v.y * v.y) * inv);
        w.z = kj * (v.z - (v.z * v.z) * inv);
        w.w = kj * (v.w - (v.w * v.w) * inv);
        T[TB(6) + i17] = w;
    }
    asm volatile("bar.sync %0, 64;" :: "r"(1 + pair) : "memory");

    if (lane >= 24) return;                 // no further barriers

    const int vp  = warp & 1;               // 0: ff+fs, 1: sf+ss
    const int sub = (lane >= 12) ? 1 : 0;   // variant within the pair
    const int l   = lane - 12 * sub;
    const int qp  = l >> 1;                 // q-pair 0..5
    const int h   = l & 1;                  // D-half
    const int q0  = 2 * qp, q1 = q0 + 1;
    const int rot = 4 * h;

    // operand tiles + output quarter per (vp, sub)
    int aT, bT, vT, outq;
    if (vp == 0) {
        if (!sub) { aT = 0; bT = 1; vT = 2; outq = 0; }   // ff: Qf·Kf^T  -> Vf
        else      { aT = 1; bT = 6; vT = 2; outq = 1; }   // fs: Kf·Qfs^T -> Vf
    } else {
        if (!sub) { aT = 4; bT = 0; vT = 5; outq = 2; }   // sf: Ks·Qf^T  -> Vs
        else      { aT = 3; bT = 4; vT = 5; outq = 3; }   // ss: Qs·Ks^T  -> Vs
    }
    const float4* Ts = T + pair * SITE_F4;
    const ulonglong2* A2 = (const ulonglong2*)(Ts + TB(aT));
    const ulonglong2* B2 = (const ulonglong2*)(Ts + TB(bT));
    const ulonglong2* V2 = (const ulonglong2*)(Ts + TB(vT));
    const int* smask = smaskP[pair];

    // ---- Scores: chunked A hoist; each B chunk feeds both q-rows ----
    float s0[12], s1[12];
    #pragma unroll
    for (int k = 0; k < 12; k++) { s0[k] = 0.0f; s1[k] = 0.0f; }

    #pragma unroll
    for (int ch = 0; ch < 2; ch++) {
        ulonglong2 a0[4], a1[4];
        int jj[4];
        #pragma unroll
        for (int i = 0; i < 4; i++) {
            jj[i] = (ch * 4 + i + rot) & 7;
            a0[i] = A2[q0 * STR4 + h * 8 + jj[i]];
            a1[i] = A2[q1 * STR4 + h * 8 + jj[i]];
        }
        #pragma unroll
        for (int k = 0; k < 12; k++) {
            unsigned long long acc0 = 0ULL, acc1 = 0ULL;
            #pragma unroll
            for (int i = 0; i < 4; i++) {
                ulonglong2 b = B2[k * STR4 + h * 8 + jj[i]];
                acc0 = fma2(a0[i].x, b.x, acc0);
                acc0 = fma2(a0[i].y, b.y, acc0);
                acc1 = fma2(a1[i].x, b.x, acc1);
                acc1 = fma2(a1[i].y, b.y, acc1);
            }
            float2 p0 = unpack2(acc0), p1 = unpack2(acc1);
            s0[k] += p0.x + p0.y;
            s1[k] += p1.x + p1.y;
        }
    }

    // cross-half reduce + scale + exact mask select
    #pragma unroll
    for (int k = 0; k < 12; k++) {
        float v0 = s0[k] + __shfl_xor_sync(0x00ffffffu, s0[k], 1);
        float v1 = s1[k] + __shfl_xor_sync(0x00ffffffu, s1[k], 1);
        s0[k] = (smask[q0 * 12 + k] == 1) ? -1e9f : v0 * 0.125f;
        s1[k] = (smask[q1 * 12 + k] == 1) ? -1e9f : v1 * 0.125f;
    }

    // ---- Softmax per row (both h-lanes redundantly); pre-scale by 1/sum ----
    float mx0 = s0[0], mx1 = s1[0];
    #pragma unroll
    for (int k = 1; k < 12; k++) { mx0 = fmaxf(mx0, s0[k]); mx1 = fmaxf(mx1, s1[k]); }
    float sum0 = 0.f, sum1 = 0.f;
    #pragma unroll
    for (int k = 0; k < 12; k++) {
        s0[k] = __expf(s0[k] - mx0); sum0 += s0[k];
        s1[k] = __expf(s1[k] - mx1); sum1 += s1[k];
    }
    const float rs0 = 1.0f / sum0, rs1 = 1.0f / sum1;
    #pragma unroll
    for (int k = 0; k < 12; k++) { s0[k] *= rs0; s1[k] *= rs1; }

    // ---- Output (k-outer): each V chunk feeds both q-rows ----
    ulonglong2 c0[8], c1[8];
    #pragma unroll
    for (int i = 0; i < 8; i++) { c0[i].x = c0[i].y = 0ULL; c1[i].x = c1[i].y = 0ULL; }

    #pragma unroll
    for (int k = 0; k < 12; k++) {
        unsigned long long z0p = pack2(s0[k], s0[k]);
        unsigned long long z1p = pack2(s1[k], s1[k]);
        #pragma unroll
        for (int i = 0; i < 8; i++) {
            ulonglong2 v = V2[k * STR4 + h * 8 + ((i + rot) & 7)];
            c0[i].x = fma2(z0p, v.x, c0[i].x);
            c0[i].y = fma2(z0p, v.y, c0[i].y);
            c1[i].x = fma2(z1p, v.x, c1[i].x);
            c1[i].y = fma2(z1p, v.y, c1[i].y);
        }
    }

    // ---- Store both rows (un-rotate); quarters ordered (ff, fs, sf, ss) ----
    float4* ob = (float4*)out + ((long long)outq * nsite + site) * 192 + h * 8;
    float4* o0 = ob + q0 * 16;
    float4* o1 = ob + q1 * 16;
    #pragma unroll
    for (int i = 0; i < 8; i++) {
        int j = (i + rot) & 7;
        float2 lo0 = unpack2(c0[i].x), hi0 = unpack2(c0[i].y);
        float2 lo1 = unpack2(c1[i].x), hi1 = unpack2(c1[i].y);
        o0[j] = make_float4(lo0.x, lo0.y, hi0.x, hi0.y);
        o1[j] = make_float4(lo1.x, lo1.y, hi1.x, hi1.y);
    }
}

extern "C" void kernel_launch(void* const* d_in, const int* in_sizes, int n_in,
                              void* d_out, int out_size) {
    const int nsite = in_sizes[0] / 768;   // B*H*L1 = 39296 (even)
    tsdp_kernel<<<nsite / 2, 128>>>(
        (const float*)d_in[0], (const float*)d_in[1], (const float*)d_in[2],
        (const float*)d_in[3], (const float*)d_in[4], (const float*)d_in[5],
        (const float*)d_in[6], (const float*)d_in[7],
        (const int*)d_in[8],
        (float*)d_out, nsite);
}